// round 5
// baseline (speedup 1.0000x reference)
#include <cuda_runtime.h>

#define PH 7
#define PW 7
#define SP 4
#define CH 10
#define FH 34
#define FW 34
#define NPIX (FH * FW)      // 1156
#define NBINS (PH * PW)     // 49
#define TPB 256
#define RPT 4               // rois per thread
#define RPB (TPB * RPT)     // 1024 rois per block
#define NPAD 10240          // padded roi stride

// scratch[(c*49+bin)*NPAD + n], f32, ~20 MB
__device__ float g_scratch[CH * NBINS * NPAD];
// per-roi separable weights: {g0, g1, g2, rowoff} per (ph|pw, n)
__device__ float4 g_wy[PH * NPAD];
__device__ float4 g_wx[PW * NPAD];

// ---------------------------------------------------------------------------
// Kernel 0: per-roi weight precompute.
// Input bounds guarantee rs*>=0 and re*<34, so every sample is inside
// (-1, F): keep==true, count==16 (folded as 1/16 into gy), lower corner
// always valid; only the y1+1/x1+1 edge check survives.
// ---------------------------------------------------------------------------
__global__ void __launch_bounds__(TPB) weights_kernel(
    const float* __restrict__ rois, int N)
{
    const int n = blockIdx.x * TPB + threadIdx.x;
    if (n >= N) return;

    const float rsw = rois[n * 5 + 1] * 0.125f;
    const float rsh = rois[n * 5 + 2] * 0.125f;
    const float rew = rois[n * 5 + 3] * 0.125f;
    const float reh = rois[n * 5 + 4] * 0.125f;

    float roi_h = reh - rsh; if (!(roi_h > 0.1f)) roi_h = 0.1f;
    float roi_w = rew - rsw; if (!(roi_w > 0.1f)) roi_w = 0.1f;

    const float bin_h = __fdiv_rn(roi_h, 7.0f);
    const float bin_w = __fdiv_rn(roi_w, 7.0f);
    const float sub_h = 0.25f * bin_h;
    const float sub_w = 0.25f * bin_w;

    #pragma unroll
    for (int ph = 0; ph < PH; ++ph) {
        const float hstart = floorf(__fadd_rn(rsh, __fmul_rn((float)ph, bin_h)));
        const int y0i = (int)hstart;
        float gy[3] = {0.f, 0.f, 0.f};
        #pragma unroll
        for (int s = 0; s < SP; ++s) {
            const float H = __fadd_rn(hstart, __fmul_rn((float)s + 0.5f, sub_h));
            const float yf = floorf(H);
            const float dy = H - yf;
            const int y1 = (int)yf;
            const int j  = y1 - y0i;                 // in {0,1}
            gy[j]     += 1.0f - dy;
            gy[j + 1] += (y1 + 1 < FH) ? dy : 0.0f;
        }
        g_wy[ph * NPAD + n] = make_float4(gy[0] * 0.0625f, gy[1] * 0.0625f,
                                          gy[2] * 0.0625f, (float)(y0i * FW));
    }
    #pragma unroll
    for (int pw = 0; pw < PW; ++pw) {
        const float wstart = floorf(__fadd_rn(rsw, __fmul_rn((float)pw, bin_w)));
        const int x0i = (int)wstart;
        float gx[3] = {0.f, 0.f, 0.f};
        #pragma unroll
        for (int s = 0; s < SP; ++s) {
            const float W = __fadd_rn(wstart, __fmul_rn((float)s + 0.5f, sub_w));
            const float xf = floorf(W);
            const float dx = W - xf;
            const int x1 = (int)xf;
            const int i  = x1 - x0i;                 // in {0,1}
            gx[i]     += 1.0f - dx;
            gx[i + 1] += (x1 + 1 < FW) ? dx : 0.0f;
        }
        g_wx[pw * NPAD + n] = make_float4(gx[0], gx[1], gx[2], (float)x0i);
    }
}

// ---------------------------------------------------------------------------
// Kernel 1: per-bin gather into scratch (coalesced n-major stores).
// ---------------------------------------------------------------------------
__global__ void __launch_bounds__(TPB) psroi_kernel(
    const float* __restrict__ ft, int N)
{
    __shared__ float smf[NPIX * CH];   // [pix][10] f32, 46.2 KB

    const int bin = blockIdx.y;
    const int ph  = bin / PW;
    const int pw  = bin - ph * PW;
    const int tid = threadIdx.x;

    // Stage the (ph,pw) slice, all 10 channels, f32 [pix][c]
    {
        const float* base = ft + (size_t)bin * NPIX;
        for (int p = tid; p < NPIX; p += TPB) {
            #pragma unroll
            for (int c = 0; c < CH; ++c)
                smf[p * CH + c] = base[(size_t)c * (NBINS * NPIX) + p];
        }
    }
    __syncthreads();

    const float4* __restrict__ wyp = g_wy + (size_t)ph * NPAD;
    const float4* __restrict__ wxp = g_wx + (size_t)pw * NPAD;

    const int nbase = blockIdx.x * RPB + tid;

    #pragma unroll 1
    for (int r = 0; r < RPT; ++r) {
        const int n = nbase + r * TPB;
        if (n >= N) break;

        const float4 wy = __ldg(&wyp[n]);
        const float4 wx = __ldg(&wxp[n]);
        const int rowbase = (int)(wy.w + wx.w);   // y0*34 + x0, exact in f32

        const float gy[3] = { wy.x, wy.y, wy.z };
        const float gx[3] = { wx.x, wx.y, wx.z };

        float acc[CH];
        #pragma unroll
        for (int c = 0; c < CH; ++c) acc[c] = 0.f;

        // Zero-skip 3x3 gather; w != 0 implies the pixel is in-range.
        #pragma unroll
        for (int j = 0; j < 3; ++j) {
            const float gyj = gy[j];
            if (gyj != 0.f) {
                const int off = (rowbase + j * FW) * CH;
                #pragma unroll
                for (int i = 0; i < 3; ++i) {
                    const float w = gyj * gx[i];
                    if (w != 0.f) {
                        const float* pp = smf + off + i * CH;  // 40B stride, 8B aligned
                        const float2 f0 = *(const float2*)(pp + 0);
                        const float2 f1 = *(const float2*)(pp + 2);
                        const float2 f2 = *(const float2*)(pp + 4);
                        const float2 f3 = *(const float2*)(pp + 6);
                        const float2 f4 = *(const float2*)(pp + 8);
                        acc[0] = fmaf(w, f0.x, acc[0]);
                        acc[1] = fmaf(w, f0.y, acc[1]);
                        acc[2] = fmaf(w, f1.x, acc[2]);
                        acc[3] = fmaf(w, f1.y, acc[3]);
                        acc[4] = fmaf(w, f2.x, acc[4]);
                        acc[5] = fmaf(w, f2.y, acc[5]);
                        acc[6] = fmaf(w, f3.x, acc[6]);
                        acc[7] = fmaf(w, f3.y, acc[7]);
                        acc[8] = fmaf(w, f4.x, acc[8]);
                        acc[9] = fmaf(w, f4.y, acc[9]);
                    }
                }
            }
        }

        float* sc = g_scratch + (size_t)bin * NPAD + n;
        #pragma unroll
        for (int c = 0; c < CH; ++c)
            sc[(size_t)c * (NBINS * NPAD)] = acc[c];
    }
}

// ---------------------------------------------------------------------------
// Kernel 2: out[n*490 + q] = scratch[q*NPAD + n], q = c*49+bin.
// 32q x 128n tiles, 256 threads; float4 LDG, scalar conflict-free STS,
// float2 coalesced STG.
// ---------------------------------------------------------------------------
#define TQ 32
#define TN 128
#define TS 129

__global__ void __launch_bounds__(256) transpose_kernel(
    float* __restrict__ out, int N)
{
    __shared__ float tile[TQ * TS];  // 16.5 KB

    const int tid   = threadIdx.x;
    const int qBase = blockIdx.y * TQ;
    const int nBase = blockIdx.x * TN;

    // Load: one float4 per (thread, row-pass); lanes cover 128 consecutive n.
    {
        const int lane = tid & 31;
        const int qrow = tid >> 5;            // 0..7
        #pragma unroll
        for (int qi = 0; qi < 4; ++qi) {
            const int q  = qrow + qi * 8;     // 0..31
            const int qg = qBase + q;
            if (qg < CH * NBINS) {
                const float4 v = __ldg((const float4*)
                    (g_scratch + (size_t)qg * NPAD + nBase + lane * 4));
                float* t = tile + q * TS + lane * 4;
                t[0] = v.x; t[1] = v.y; t[2] = v.z; t[3] = v.w;
            }
        }
    }
    __syncthreads();

    // Store: half-warp covers a 128B contiguous q-span of one output row.
    {
        const int c2 = tid & 15;              // q pair: qBase + 2*c2
        const int nr = tid >> 4;              // 0..15
        const int q0 = qBase + 2 * c2;
        if (q0 + 1 < CH * NBINS) {
            #pragma unroll
            for (int k = 0; k < 8; ++k) {
                const int nl = nr + k * 16;   // 0..127
                const int ng = nBase + nl;
                if (ng < N) {
                    float2 v;
                    v.x = tile[(2 * c2)     * TS + nl];
                    v.y = tile[(2 * c2 + 1) * TS + nl];
                    *(float2*)(out + (size_t)ng * (CH * NBINS) + q0) = v;
                }
            }
        }
    }
}

extern "C" void kernel_launch(void* const* d_in, const int* in_sizes, int n_in,
                              void* d_out, int out_size)
{
    const float* ft   = (const float*)d_in[0];   // 490*34*34 floats
    const float* rois = (const float*)d_in[1];   // N*5 floats
    float* out        = (float*)d_out;           // N*10*49 floats

    const int N = in_sizes[1] / 5;

    weights_kernel<<<(N + TPB - 1) / TPB, TPB>>>(rois, N);

    dim3 grid1((N + RPB - 1) / RPB, NBINS);
    psroi_kernel<<<grid1, TPB>>>(ft, N);

    dim3 grid2((N + TN - 1) / TN, (CH * NBINS + TQ - 1) / TQ);
    transpose_kernel<<<grid2, 256>>>(out, N);
}

// round 6
// speedup vs baseline: 1.0641x; 1.0641x over previous
#include <cuda_runtime.h>

#define PH 7
#define PW 7
#define SP 4
#define CH 10
#define FH 34
#define FW 34
#define NPIX (FH * FW)      // 1156
#define NBINS (PH * PW)     // 49
#define TPB 256
#define RPT 4               // rois per thread
#define RPB (TPB * RPT)     // 1024 rois per block
#define NPAD 10240          // padded roi stride

// scratch[(c*49+bin)*NPAD + n], f32, ~20 MB
__device__ float g_scratch[CH * NBINS * NPAD];
// per-roi separable weights: {g0, g1, g2, rowoff} per (ph|pw, n)
__device__ float4 g_wy[PH * NPAD];
__device__ float4 g_wx[PW * NPAD];

// ---------------------------------------------------------------------------
// Kernel 0: per-roi weight precompute, one thread per (n, p, axis).
// grid = (ceil(N/256), 14); blockIdx.y in [0,7) -> gy[ph], [7,14) -> gx[pw].
// Input bounds guarantee rs*>=0 and re*<34, so every sample is inside
// (-1, F): keep==true, count==16 (folded as 1/16 into gy), lower corner
// always valid; only the y1+1/x1+1 edge check survives.
// ---------------------------------------------------------------------------
__global__ void __launch_bounds__(TPB) weights_kernel(
    const float* __restrict__ rois, int N)
{
    const int n = blockIdx.x * TPB + threadIdx.x;
    if (n >= N) return;
    const int k = blockIdx.y;                 // 0..13

    const bool isY = (k < PH);
    const int  p   = isY ? k : k - PH;

    const float rs = rois[n * 5 + (isY ? 2 : 1)] * 0.125f;
    const float re = rois[n * 5 + (isY ? 4 : 3)] * 0.125f;

    float roi = re - rs; if (!(roi > 0.1f)) roi = 0.1f;
    const float binsz = __fdiv_rn(roi, 7.0f);
    const float subsz = 0.25f * binsz;

    const float start = floorf(__fadd_rn(rs, __fmul_rn((float)p, binsz)));
    const int v0 = (int)start;

    float g[3] = {0.f, 0.f, 0.f};
    #pragma unroll
    for (int s = 0; s < SP; ++s) {
        const float P  = __fadd_rn(start, __fmul_rn((float)s + 0.5f, subsz));
        const float pf = floorf(P);
        const float d  = P - pf;
        const int v1 = (int)pf;
        const int j  = v1 - v0;                 // in {0,1}
        g[j]     += 1.0f - d;
        g[j + 1] += (v1 + 1 < FH) ? d : 0.0f;   // FH == FW == 34
    }

    if (isY)
        g_wy[p * NPAD + n] = make_float4(g[0] * 0.0625f, g[1] * 0.0625f,
                                         g[2] * 0.0625f, (float)(v0 * FW));
    else
        g_wx[p * NPAD + n] = make_float4(g[0], g[1], g[2], (float)v0);
}

// ---------------------------------------------------------------------------
// Kernel 1: per-bin gather into scratch (coalesced n-major stores).
// ---------------------------------------------------------------------------
__global__ void __launch_bounds__(TPB) psroi_kernel(
    const float* __restrict__ ft, int N)
{
    __shared__ float smf[NPIX * CH];   // [pix][10] f32, 46.2 KB

    const int bin = blockIdx.y;
    const int ph  = bin / PW;
    const int pw  = bin - ph * PW;
    const int tid = threadIdx.x;

    // Stage the (ph,pw) slice, all 10 channels, f32 [pix][c]
    {
        const float* base = ft + (size_t)bin * NPIX;
        for (int p = tid; p < NPIX; p += TPB) {
            #pragma unroll
            for (int c = 0; c < CH; ++c)
                smf[p * CH + c] = base[(size_t)c * (NBINS * NPIX) + p];
        }
    }
    __syncthreads();

    const float4* __restrict__ wyp = g_wy + (size_t)ph * NPAD;
    const float4* __restrict__ wxp = g_wx + (size_t)pw * NPAD;

    const int nbase = blockIdx.x * RPB + tid;

    #pragma unroll 1
    for (int r = 0; r < RPT; ++r) {
        const int n = nbase + r * TPB;
        if (n >= N) break;

        const float4 wy = __ldg(&wyp[n]);
        const float4 wx = __ldg(&wxp[n]);
        const int rowbase = (int)(wy.w + wx.w);   // y0*34 + x0, exact in f32

        const float gy[3] = { wy.x, wy.y, wy.z };
        const float gx[3] = { wx.x, wx.y, wx.z };

        float acc[CH];
        #pragma unroll
        for (int c = 0; c < CH; ++c) acc[c] = 0.f;

        // Zero-skip 3x3 gather; w != 0 implies the pixel is in-range.
        #pragma unroll
        for (int j = 0; j < 3; ++j) {
            const float gyj = gy[j];
            if (gyj != 0.f) {
                const int off = (rowbase + j * FW) * CH;
                #pragma unroll
                for (int i = 0; i < 3; ++i) {
                    const float w = gyj * gx[i];
                    if (w != 0.f) {
                        const float* pp = smf + off + i * CH;  // 40B stride, 8B aligned
                        const float2 f0 = *(const float2*)(pp + 0);
                        const float2 f1 = *(const float2*)(pp + 2);
                        const float2 f2 = *(const float2*)(pp + 4);
                        const float2 f3 = *(const float2*)(pp + 6);
                        const float2 f4 = *(const float2*)(pp + 8);
                        acc[0] = fmaf(w, f0.x, acc[0]);
                        acc[1] = fmaf(w, f0.y, acc[1]);
                        acc[2] = fmaf(w, f1.x, acc[2]);
                        acc[3] = fmaf(w, f1.y, acc[3]);
                        acc[4] = fmaf(w, f2.x, acc[4]);
                        acc[5] = fmaf(w, f2.y, acc[5]);
                        acc[6] = fmaf(w, f3.x, acc[6]);
                        acc[7] = fmaf(w, f3.y, acc[7]);
                        acc[8] = fmaf(w, f4.x, acc[8]);
                        acc[9] = fmaf(w, f4.y, acc[9]);
                    }
                }
            }
        }

        float* sc = g_scratch + (size_t)bin * NPAD + n;
        #pragma unroll
        for (int c = 0; c < CH; ++c)
            sc[(size_t)c * (NBINS * NPAD)] = acc[c];
    }
}

// ---------------------------------------------------------------------------
// Kernel 2: out[n*490 + q] = scratch[q*NPAD + n], q = c*49+bin.
// 32q x 128n tiles, 256 threads; float4 LDG, scalar conflict-free STS,
// float2 coalesced STG.
// ---------------------------------------------------------------------------
#define TQ 32
#define TN 128
#define TS 129

__global__ void __launch_bounds__(256) transpose_kernel(
    float* __restrict__ out, int N)
{
    __shared__ float tile[TQ * TS];  // 16.5 KB

    const int tid   = threadIdx.x;
    const int qBase = blockIdx.y * TQ;
    const int nBase = blockIdx.x * TN;

    // Load: one float4 per (thread, row-pass); lanes cover 128 consecutive n.
    {
        const int lane = tid & 31;
        const int qrow = tid >> 5;            // 0..7
        #pragma unroll
        for (int qi = 0; qi < 4; ++qi) {
            const int q  = qrow + qi * 8;     // 0..31
            const int qg = qBase + q;
            if (qg < CH * NBINS) {
                const float4 v = __ldg((const float4*)
                    (g_scratch + (size_t)qg * NPAD + nBase + lane * 4));
                float* t = tile + q * TS + lane * 4;
                t[0] = v.x; t[1] = v.y; t[2] = v.z; t[3] = v.w;
            }
        }
    }
    __syncthreads();

    // Store: half-warp covers a 128B contiguous q-span of one output row.
    {
        const int c2 = tid & 15;              // q pair: qBase + 2*c2
        const int nr = tid >> 4;              // 0..15
        const int q0 = qBase + 2 * c2;
        if (q0 + 1 < CH * NBINS) {
            #pragma unroll
            for (int k = 0; k < 8; ++k) {
                const int nl = nr + k * 16;   // 0..127
                const int ng = nBase + nl;
                if (ng < N) {
                    float2 v;
                    v.x = tile[(2 * c2)     * TS + nl];
                    v.y = tile[(2 * c2 + 1) * TS + nl];
                    *(float2*)(out + (size_t)ng * (CH * NBINS) + q0) = v;
                }
            }
        }
    }
}

extern "C" void kernel_launch(void* const* d_in, const int* in_sizes, int n_in,
                              void* d_out, int out_size)
{
    const float* ft   = (const float*)d_in[0];   // 490*34*34 floats
    const float* rois = (const float*)d_in[1];   // N*5 floats
    float* out        = (float*)d_out;           // N*10*49 floats

    const int N = in_sizes[1] / 5;

    dim3 grid0((N + TPB - 1) / TPB, PH + PW);
    weights_kernel<<<grid0, TPB>>>(rois, N);

    dim3 grid1((N + RPB - 1) / RPB, NBINS);
    psroi_kernel<<<grid1, TPB>>>(ft, N);

    dim3 grid2((N + TN - 1) / TN, (CH * NBINS + TQ - 1) / TQ);
    transpose_kernel<<<grid2, 256>>>(out, N);
}

// round 7
// speedup vs baseline: 1.0717x; 1.0072x over previous
#include <cuda_runtime.h>

#define PH 7
#define PW 7
#define SP 4
#define CH 10
#define FH 34
#define FW 34
#define NPIX (FH * FW)      // 1156
#define NBINS (PH * PW)     // 49
#define TPB 256
#define RPT 4               // rois per thread
#define RPB (TPB * RPT)     // 1024 rois per block
#define NPAD 10240          // padded roi stride

// scratch[(c*49+bin)*NPAD + n], f32, ~20 MB
__device__ float g_scratch[CH * NBINS * NPAD];
// per-roi separable weights: {g0, g1, g2, rowoff} per (ph|pw, n)
__device__ float4 g_wy[PH * NPAD];
__device__ float4 g_wx[PW * NPAD];

// ---------------------------------------------------------------------------
// Kernel 0: per-roi weight precompute, one thread per (n, p, axis).
// grid = (ceil(N/256), 14); blockIdx.y in [0,7) -> gy[ph], [7,14) -> gx[pw].
// CRITICAL: accumulators are scalars with predicated selects — NO dynamic
// register-array indexing (that spilled to local memory and cost 8.9us).
// ---------------------------------------------------------------------------
__global__ void __launch_bounds__(TPB) weights_kernel(
    const float* __restrict__ rois, int N)
{
    const int n = blockIdx.x * TPB + threadIdx.x;
    if (n >= N) return;
    const int k = blockIdx.y;                 // 0..13

    const bool isY = (k < PH);
    const int  p   = isY ? k : k - PH;

    const float rs = rois[n * 5 + (isY ? 2 : 1)] * 0.125f;
    const float re = rois[n * 5 + (isY ? 4 : 3)] * 0.125f;

    float roi = re - rs; if (!(roi > 0.1f)) roi = 0.1f;
    const float binsz = __fdiv_rn(roi, 7.0f);
    const float subsz = 0.25f * binsz;

    const float start = floorf(__fadd_rn(rs, __fmul_rn((float)p, binsz)));
    const int v0 = (int)start;

    float g0 = 0.f, g1 = 0.f, g2 = 0.f;
    #pragma unroll
    for (int s = 0; s < SP; ++s) {
        const float P  = __fadd_rn(start, __fmul_rn((float)s + 0.5f, subsz));
        const float pf = floorf(P);
        const float d  = P - pf;
        const int v1 = (int)pf;
        const bool hi = (v1 != v0);             // sample fell in row v0+1
        const float w1 = 1.0f - d;
        const float w2 = (v1 + 1 < FH) ? d : 0.0f;   // FH == FW == 34
        g0 += hi ? 0.0f : w1;
        g1 += hi ? w1   : w2;
        g2 += hi ? w2   : 0.0f;
    }

    if (isY)
        g_wy[p * NPAD + n] = make_float4(g0 * 0.0625f, g1 * 0.0625f,
                                         g2 * 0.0625f, (float)(v0 * FW));
    else
        g_wx[p * NPAD + n] = make_float4(g0, g1, g2, (float)v0);
}

// ---------------------------------------------------------------------------
// Kernel 1: per-bin gather into scratch (coalesced n-major stores).
// ---------------------------------------------------------------------------
__global__ void __launch_bounds__(TPB) psroi_kernel(
    const float* __restrict__ ft, int N)
{
    __shared__ float smf[NPIX * CH];   // [pix][10] f32, 46.2 KB

    const int bin = blockIdx.y;
    const int ph  = bin / PW;
    const int pw  = bin - ph * PW;
    const int tid = threadIdx.x;

    // Stage the (ph,pw) slice, all 10 channels, f32 [pix][c]
    {
        const float* base = ft + (size_t)bin * NPIX;
        for (int p = tid; p < NPIX; p += TPB) {
            #pragma unroll
            for (int c = 0; c < CH; ++c)
                smf[p * CH + c] = base[(size_t)c * (NBINS * NPIX) + p];
        }
    }
    __syncthreads();

    const float4* __restrict__ wyp = g_wy + (size_t)ph * NPAD;
    const float4* __restrict__ wxp = g_wx + (size_t)pw * NPAD;

    const int nbase = blockIdx.x * RPB + tid;

    #pragma unroll 1
    for (int r = 0; r < RPT; ++r) {
        const int n = nbase + r * TPB;
        if (n >= N) break;

        const float4 wy = __ldg(&wyp[n]);
        const float4 wx = __ldg(&wxp[n]);
        const int rowbase = (int)(wy.w + wx.w);   // y0*34 + x0, exact in f32

        const float gy[3] = { wy.x, wy.y, wy.z };
        const float gx[3] = { wx.x, wx.y, wx.z };

        float acc[CH];
        #pragma unroll
        for (int c = 0; c < CH; ++c) acc[c] = 0.f;

        // Zero-skip 3x3 gather; w != 0 implies the pixel is in-range.
        #pragma unroll
        for (int j = 0; j < 3; ++j) {
            const float gyj = gy[j];
            if (gyj != 0.f) {
                const int off = (rowbase + j * FW) * CH;
                #pragma unroll
                for (int i = 0; i < 3; ++i) {
                    const float w = gyj * gx[i];
                    if (w != 0.f) {
                        const float* pp = smf + off + i * CH;  // 40B stride, 8B aligned
                        const float2 f0 = *(const float2*)(pp + 0);
                        const float2 f1 = *(const float2*)(pp + 2);
                        const float2 f2 = *(const float2*)(pp + 4);
                        const float2 f3 = *(const float2*)(pp + 6);
                        const float2 f4 = *(const float2*)(pp + 8);
                        acc[0] = fmaf(w, f0.x, acc[0]);
                        acc[1] = fmaf(w, f0.y, acc[1]);
                        acc[2] = fmaf(w, f1.x, acc[2]);
                        acc[3] = fmaf(w, f1.y, acc[3]);
                        acc[4] = fmaf(w, f2.x, acc[4]);
                        acc[5] = fmaf(w, f2.y, acc[5]);
                        acc[6] = fmaf(w, f3.x, acc[6]);
                        acc[7] = fmaf(w, f3.y, acc[7]);
                        acc[8] = fmaf(w, f4.x, acc[8]);
                        acc[9] = fmaf(w, f4.y, acc[9]);
                    }
                }
            }
        }

        float* sc = g_scratch + (size_t)bin * NPAD + n;
        #pragma unroll
        for (int c = 0; c < CH; ++c)
            sc[(size_t)c * (NBINS * NPAD)] = acc[c];
    }
}

// ---------------------------------------------------------------------------
// Kernel 2: out[n*490 + q] = scratch[q*NPAD + n], q = c*49+bin.
// 2 tiles of 32q x 128n per block, pipelined: all 8 LDG.128 in flight before
// the single barrier (2x MLP, half the blocks/barriers vs 1-tile version).
// ---------------------------------------------------------------------------
#define TQ 32
#define TN 128
#define TS 129

__global__ void __launch_bounds__(256) transpose_kernel(
    float* __restrict__ out, int N)
{
    __shared__ float tile[2][TQ * TS];  // 33 KB

    const int tid    = threadIdx.x;
    const int qBase  = blockIdx.y * TQ;
    const int nBase0 = blockIdx.x * (2 * TN);

    // Load both tiles: 8 independent LDG.128 per thread, then STS.
    {
        const int lane = tid & 31;
        const int qrow = tid >> 5;            // 0..7
        float4 v[2][4];
        #pragma unroll
        for (int t = 0; t < 2; ++t) {
            const int nB = nBase0 + t * TN;
            #pragma unroll
            for (int qi = 0; qi < 4; ++qi) {
                const int qg = qBase + qrow + qi * 8;
                // scratch is NPAD-padded in n; q always < 490 here since
                // grid.y * TQ covers exactly 490 = 16*32 - 22 (guard below)
                v[t][qi] = (qg < CH * NBINS)
                    ? __ldg((const float4*)(g_scratch + (size_t)qg * NPAD + nB + lane * 4))
                    : make_float4(0.f, 0.f, 0.f, 0.f);
            }
        }
        #pragma unroll
        for (int t = 0; t < 2; ++t) {
            #pragma unroll
            for (int qi = 0; qi < 4; ++qi) {
                const int q = qrow + qi * 8;
                float* d = tile[t] + q * TS + lane * 4;
                d[0] = v[t][qi].x; d[1] = v[t][qi].y;
                d[2] = v[t][qi].z; d[3] = v[t][qi].w;
            }
        }
    }
    __syncthreads();

    // Store: half-warp covers a 128B contiguous q-span of one output row.
    {
        const int c2 = tid & 15;              // q pair: qBase + 2*c2
        const int nr = tid >> 4;              // 0..15
        const int q0 = qBase + 2 * c2;
        if (q0 + 1 < CH * NBINS) {
            #pragma unroll
            for (int t = 0; t < 2; ++t) {
                const int nB = nBase0 + t * TN;
                #pragma unroll
                for (int k = 0; k < 8; ++k) {
                    const int nl = nr + k * 16;   // 0..127
                    const int ng = nB + nl;
                    if (ng < N) {
                        float2 v;
                        v.x = tile[t][(2 * c2)     * TS + nl];
                        v.y = tile[t][(2 * c2 + 1) * TS + nl];
                        *(float2*)(out + (size_t)ng * (CH * NBINS) + q0) = v;
                    }
                }
            }
        }
    }
}

extern "C" void kernel_launch(void* const* d_in, const int* in_sizes, int n_in,
                              void* d_out, int out_size)
{
    const float* ft   = (const float*)d_in[0];   // 490*34*34 floats
    const float* rois = (const float*)d_in[1];   // N*5 floats
    float* out        = (float*)d_out;           // N*10*49 floats

    const int N = in_sizes[1] / 5;

    dim3 grid0((N + TPB - 1) / TPB, PH + PW);
    weights_kernel<<<grid0, TPB>>>(rois, N);

    dim3 grid1((N + RPB - 1) / RPB, NBINS);
    psroi_kernel<<<grid1, TPB>>>(ft, N);

    dim3 grid2((N + 2 * TN - 1) / (2 * TN), (CH * NBINS + TQ - 1) / TQ);
    transpose_kernel<<<grid2, 256>>>(out, N);
}

// round 8
// speedup vs baseline: 1.1419x; 1.0655x over previous
#include <cuda_runtime.h>

#define PH 7
#define PW 7
#define SP 4
#define CH 10
#define FH 34
#define FW 34
#define NPIX (FH * FW)      // 1156
#define NBINS (PH * PW)     // 49
#define TPB 256
#define RPT 4               // rois per thread
#define RPB (TPB * RPT)     // 1024 rois per block
#define NPAD 10240          // padded roi stride

// scratch[(c*49+bin)*NPAD + n], f32, ~20 MB
__device__ float g_scratch[CH * NBINS * NPAD];

// ---------------------------------------------------------------------------
// Kernel 1: per-bin gather into scratch (coalesced n-major stores).
// Weights computed inline per (roi,bin) with BRANCHLESS SCALAR accumulators
// (dynamic-index register arrays spill to local memory — proven 2x cost).
// Input bounds guarantee rs*>=0 and re*<34: every sample is inside (-1,F),
// keep==true, count==16 (folded as 1/16), lower bilinear corner always valid.
// ---------------------------------------------------------------------------
__global__ void __launch_bounds__(TPB) psroi_kernel(
    const float* __restrict__ ft,
    const float* __restrict__ rois,
    int N)
{
    __shared__ float smf[NPIX * CH];   // [pix][10] f32, 46.2 KB

    const int bin = blockIdx.y;
    const int ph  = bin / PW;
    const int pw  = bin - ph * PW;
    const int tid = threadIdx.x;

    // Stage the (ph,pw) slice, all 10 channels, f32 [pix][c]
    {
        const float* base = ft + (size_t)bin * NPIX;
        for (int p = tid; p < NPIX; p += TPB) {
            #pragma unroll
            for (int c = 0; c < CH; ++c)
                smf[p * CH + c] = base[(size_t)c * (NBINS * NPIX) + p];
        }
    }
    __syncthreads();

    const int nbase = blockIdx.x * RPB + tid;

    #pragma unroll 1
    for (int r = 0; r < RPT; ++r) {
        const int n = nbase + r * TPB;
        if (n >= N) break;

        // ---- Inline separable weights (branchless scalars, IEEE ops) ----
        const float rsw = __ldg(&rois[n * 5 + 1]) * 0.125f;
        const float rsh = __ldg(&rois[n * 5 + 2]) * 0.125f;
        const float rew = __ldg(&rois[n * 5 + 3]) * 0.125f;
        const float reh = __ldg(&rois[n * 5 + 4]) * 0.125f;

        float roi_h = reh - rsh; if (!(roi_h > 0.1f)) roi_h = 0.1f;
        float roi_w = rew - rsw; if (!(roi_w > 0.1f)) roi_w = 0.1f;

        const float bin_h = __fdiv_rn(roi_h, 7.0f);
        const float bin_w = __fdiv_rn(roi_w, 7.0f);
        const float sub_h = 0.25f * bin_h;
        const float sub_w = 0.25f * bin_w;

        const float hstart = floorf(__fadd_rn(rsh, __fmul_rn((float)ph, bin_h)));
        const float wstart = floorf(__fadd_rn(rsw, __fmul_rn((float)pw, bin_w)));
        const int y0i = (int)hstart;
        const int x0i = (int)wstart;

        float gy0 = 0.f, gy1 = 0.f, gy2 = 0.f;
        float gx0 = 0.f, gx1 = 0.f, gx2 = 0.f;

        #pragma unroll
        for (int s = 0; s < SP; ++s) {
            const float fs = (float)s + 0.5f;
            {
                const float H  = __fadd_rn(hstart, __fmul_rn(fs, sub_h));
                const float pf = floorf(H);
                const float d  = H - pf;
                const int v1 = (int)pf;
                const bool hi = (v1 != y0i);            // landed in row y0+1
                const float w1 = 1.0f - d;
                const float w2 = (v1 + 1 < FH) ? d : 0.0f;
                gy0 += hi ? 0.0f : w1;
                gy1 += hi ? w1   : w2;
                gy2 += hi ? w2   : 0.0f;
            }
            {
                const float W  = __fadd_rn(wstart, __fmul_rn(fs, sub_w));
                const float pf = floorf(W);
                const float d  = W - pf;
                const int v1 = (int)pf;
                const bool hi = (v1 != x0i);
                const float w1 = 1.0f - d;
                const float w2 = (v1 + 1 < FW) ? d : 0.0f;
                gx0 += hi ? 0.0f : w1;
                gx1 += hi ? w1   : w2;
                gx2 += hi ? w2   : 0.0f;
            }
        }
        // fold 1/count = 1/16 (exact) into gy
        gy0 *= 0.0625f; gy1 *= 0.0625f; gy2 *= 0.0625f;

        const float gy[3] = { gy0, gy1, gy2 };
        const float gx[3] = { gx0, gx1, gx2 };
        const int rowbase = y0i * FW + x0i;

        float acc[CH];
        #pragma unroll
        for (int c = 0; c < CH; ++c) acc[c] = 0.f;

        // Zero-skip 3x3 gather; w != 0 implies the pixel is in-range.
        #pragma unroll
        for (int j = 0; j < 3; ++j) {
            const float gyj = gy[j];
            if (gyj != 0.f) {
                const int off = (rowbase + j * FW) * CH;
                #pragma unroll
                for (int i = 0; i < 3; ++i) {
                    const float w = gyj * gx[i];
                    if (w != 0.f) {
                        const float* pp = smf + off + i * CH;  // 40B stride, 8B aligned
                        const float2 f0 = *(const float2*)(pp + 0);
                        const float2 f1 = *(const float2*)(pp + 2);
                        const float2 f2 = *(const float2*)(pp + 4);
                        const float2 f3 = *(const float2*)(pp + 6);
                        const float2 f4 = *(const float2*)(pp + 8);
                        acc[0] = fmaf(w, f0.x, acc[0]);
                        acc[1] = fmaf(w, f0.y, acc[1]);
                        acc[2] = fmaf(w, f1.x, acc[2]);
                        acc[3] = fmaf(w, f1.y, acc[3]);
                        acc[4] = fmaf(w, f2.x, acc[4]);
                        acc[5] = fmaf(w, f2.y, acc[5]);
                        acc[6] = fmaf(w, f3.x, acc[6]);
                        acc[7] = fmaf(w, f3.y, acc[7]);
                        acc[8] = fmaf(w, f4.x, acc[8]);
                        acc[9] = fmaf(w, f4.y, acc[9]);
                    }
                }
            }
        }

        float* sc = g_scratch + (size_t)bin * NPAD + n;
        #pragma unroll
        for (int c = 0; c < CH; ++c)
            sc[(size_t)c * (NBINS * NPAD)] = acc[c];
    }
}

// ---------------------------------------------------------------------------
// Kernel 2: out[n*490 + q] = scratch[q*NPAD + n], q = c*49+bin.
// Single 32q x 128n tile per block (proven best: latency/occupancy bound).
// float4 LDG, scalar conflict-free STS, float2 coalesced STG.
// ---------------------------------------------------------------------------
#define TQ 32
#define TN 128
#define TS 129

__global__ void __launch_bounds__(256) transpose_kernel(
    float* __restrict__ out, int N)
{
    __shared__ float tile[TQ * TS];  // 16.5 KB

    const int tid   = threadIdx.x;
    const int qBase = blockIdx.y * TQ;
    const int nBase = blockIdx.x * TN;

    // Load: one float4 per (thread, row-pass); lanes cover 128 consecutive n.
    {
        const int lane = tid & 31;
        const int qrow = tid >> 5;            // 0..7
        #pragma unroll
        for (int qi = 0; qi < 4; ++qi) {
            const int q  = qrow + qi * 8;     // 0..31
            const int qg = qBase + q;
            if (qg < CH * NBINS) {
                const float4 v = __ldg((const float4*)
                    (g_scratch + (size_t)qg * NPAD + nBase + lane * 4));
                float* t = tile + q * TS + lane * 4;
                t[0] = v.x; t[1] = v.y; t[2] = v.z; t[3] = v.w;
            }
        }
    }
    __syncthreads();

    // Store: half-warp covers a 128B contiguous q-span of one output row.
    {
        const int c2 = tid & 15;              // q pair: qBase + 2*c2
        const int nr = tid >> 4;              // 0..15
        const int q0 = qBase + 2 * c2;
        if (q0 + 1 < CH * NBINS) {
            #pragma unroll
            for (int k = 0; k < 8; ++k) {
                const int nl = nr + k * 16;   // 0..127
                const int ng = nBase + nl;
                if (ng < N) {
                    float2 v;
                    v.x = tile[(2 * c2)     * TS + nl];
                    v.y = tile[(2 * c2 + 1) * TS + nl];
                    *(float2*)(out + (size_t)ng * (CH * NBINS) + q0) = v;
                }
            }
        }
    }
}

extern "C" void kernel_launch(void* const* d_in, const int* in_sizes, int n_in,
                              void* d_out, int out_size)
{
    const float* ft   = (const float*)d_in[0];   // 490*34*34 floats
    const float* rois = (const float*)d_in[1];   // N*5 floats
    float* out        = (float*)d_out;           // N*10*49 floats

    const int N = in_sizes[1] / 5;

    dim3 grid1((N + RPB - 1) / RPB, NBINS);
    psroi_kernel<<<grid1, TPB>>>(ft, rois, N);

    dim3 grid2((N + TN - 1) / TN, (CH * NBINS + TQ - 1) / TQ);
    transpose_kernel<<<grid2, 256>>>(out, N);
}

// round 9
// speedup vs baseline: 1.1469x; 1.0044x over previous
#include <cuda_runtime.h>

#define PH 7
#define PW 7
#define SP 4
#define CH 10
#define FH 34
#define FW 34
#define NPIX (FH * FW)      // 1156
#define NBINS (PH * PW)     // 49
#define TPB 256
#define RPT 4               // rois per thread
#define RPB (TPB * RPT)     // 1024 rois per block
#define NPAD 10240          // padded roi stride

// scratch[(c*49+bin)*NPAD + n], f32, ~20 MB
__device__ float g_scratch[CH * NBINS * NPAD];
// per-roi separable weights: {g0, g1, g2, rowoff} per (ph|pw, n)
__device__ float4 g_wy[PH * NPAD];
__device__ float4 g_wx[PW * NPAD];

// ---------------------------------------------------------------------------
// Kernel 0: per-roi weight precompute. grid = (ceil(N/2/256), 14);
// blockIdx.y in [0,7) -> gy[ph], [7,14) -> gx[pw]. Each thread computes TWO
// rois (ILP-2: the div/floor chain is serial and latency-bound).
// Branchless SCALAR accumulators — dynamic-index register arrays spill to
// local memory (proven 2x cost).
// Input bounds: rs*>=0, re*<34 -> every sample inside (-1,F), keep==true,
// count==16 (folded as 1/16 into gy), lower bilinear corner always valid.
// ---------------------------------------------------------------------------
__global__ void __launch_bounds__(TPB) weights_kernel(
    const float* __restrict__ rois, int N, int half)
{
    const int n0 = blockIdx.x * TPB + threadIdx.x;
    if (n0 >= half) return;
    const int k = blockIdx.y;                 // 0..13

    const bool isY = (k < PH);
    const int  p   = isY ? k : k - PH;
    const float fp = (float)p;

    #pragma unroll
    for (int t = 0; t < 2; ++t) {
        const int n = n0 + t * half;
        if (n >= N) break;

        const float rs = __ldg(&rois[n * 5 + (isY ? 2 : 1)]) * 0.125f;
        const float re = __ldg(&rois[n * 5 + (isY ? 4 : 3)]) * 0.125f;

        float roi = re - rs; if (!(roi > 0.1f)) roi = 0.1f;
        const float binsz = __fdiv_rn(roi, 7.0f);
        const float subsz = 0.25f * binsz;

        const float start = floorf(__fadd_rn(rs, __fmul_rn(fp, binsz)));
        const int v0 = (int)start;

        float g0 = 0.f, g1 = 0.f, g2 = 0.f;
        #pragma unroll
        for (int s = 0; s < SP; ++s) {
            const float P  = __fadd_rn(start, __fmul_rn((float)s + 0.5f, subsz));
            const float pf = floorf(P);
            const float d  = P - pf;
            const int v1 = (int)pf;
            const bool hi = (v1 != v0);             // sample fell in row v0+1
            const float w1 = 1.0f - d;
            const float w2 = (v1 + 1 < FH) ? d : 0.0f;   // FH == FW == 34
            g0 += hi ? 0.0f : w1;
            g1 += hi ? w1   : w2;
            g2 += hi ? w2   : 0.0f;
        }

        if (isY)
            g_wy[p * NPAD + n] = make_float4(g0 * 0.0625f, g1 * 0.0625f,
                                             g2 * 0.0625f, (float)(v0 * FW));
        else
            g_wx[p * NPAD + n] = make_float4(g0, g1, g2, (float)v0);
    }
}

// ---------------------------------------------------------------------------
// Kernel 1: per-bin gather into scratch (coalesced n-major stores).
// Reads precomputed weight tables (one LDG.128 per axis per roi).
// ---------------------------------------------------------------------------
__global__ void __launch_bounds__(TPB) psroi_kernel(
    const float* __restrict__ ft, int N)
{
    __shared__ float smf[NPIX * CH];   // [pix][10] f32, 46.2 KB

    const int bin = blockIdx.y;
    const int ph  = bin / PW;
    const int pw  = bin - ph * PW;
    const int tid = threadIdx.x;

    // Stage the (ph,pw) slice, all 10 channels, f32 [pix][c]
    {
        const float* base = ft + (size_t)bin * NPIX;
        for (int p = tid; p < NPIX; p += TPB) {
            #pragma unroll
            for (int c = 0; c < CH; ++c)
                smf[p * CH + c] = base[(size_t)c * (NBINS * NPIX) + p];
        }
    }
    __syncthreads();

    const float4* __restrict__ wyp = g_wy + (size_t)ph * NPAD;
    const float4* __restrict__ wxp = g_wx + (size_t)pw * NPAD;

    const int nbase = blockIdx.x * RPB + tid;

    #pragma unroll 1
    for (int r = 0; r < RPT; ++r) {
        const int n = nbase + r * TPB;
        if (n >= N) break;

        const float4 wy = __ldg(&wyp[n]);
        const float4 wx = __ldg(&wxp[n]);
        const int rowbase = (int)(wy.w + wx.w);   // y0*34 + x0, exact in f32

        const float gy[3] = { wy.x, wy.y, wy.z };
        const float gx[3] = { wx.x, wx.y, wx.z };

        float acc[CH];
        #pragma unroll
        for (int c = 0; c < CH; ++c) acc[c] = 0.f;

        // Zero-skip 3x3 gather; w != 0 implies the pixel is in-range.
        #pragma unroll
        for (int j = 0; j < 3; ++j) {
            const float gyj = gy[j];
            if (gyj != 0.f) {
                const int off = (rowbase + j * FW) * CH;
                #pragma unroll
                for (int i = 0; i < 3; ++i) {
                    const float w = gyj * gx[i];
                    if (w != 0.f) {
                        const float* pp = smf + off + i * CH;  // 40B stride, 8B aligned
                        const float2 f0 = *(const float2*)(pp + 0);
                        const float2 f1 = *(const float2*)(pp + 2);
                        const float2 f2 = *(const float2*)(pp + 4);
                        const float2 f3 = *(const float2*)(pp + 6);
                        const float2 f4 = *(const float2*)(pp + 8);
                        acc[0] = fmaf(w, f0.x, acc[0]);
                        acc[1] = fmaf(w, f0.y, acc[1]);
                        acc[2] = fmaf(w, f1.x, acc[2]);
                        acc[3] = fmaf(w, f1.y, acc[3]);
                        acc[4] = fmaf(w, f2.x, acc[4]);
                        acc[5] = fmaf(w, f2.y, acc[5]);
                        acc[6] = fmaf(w, f3.x, acc[6]);
                        acc[7] = fmaf(w, f3.y, acc[7]);
                        acc[8] = fmaf(w, f4.x, acc[8]);
                        acc[9] = fmaf(w, f4.y, acc[9]);
                    }
                }
            }
        }

        float* sc = g_scratch + (size_t)bin * NPAD + n;
        #pragma unroll
        for (int c = 0; c < CH; ++c)
            sc[(size_t)c * (NBINS * NPAD)] = acc[c];
    }
}

// ---------------------------------------------------------------------------
// Kernel 2: out[n*490 + q] = scratch[q*NPAD + n], q = c*49+bin.
// Single 32q x 128n tile per block (proven best: latency/occupancy bound).
// float4 LDG, scalar conflict-free STS, float2 coalesced STG.
// ---------------------------------------------------------------------------
#define TQ 32
#define TN 128
#define TS 129

__global__ void __launch_bounds__(256) transpose_kernel(
    float* __restrict__ out, int N)
{
    __shared__ float tile[TQ * TS];  // 16.5 KB

    const int tid   = threadIdx.x;
    const int qBase = blockIdx.y * TQ;
    const int nBase = blockIdx.x * TN;

    // Load: one float4 per (thread, row-pass); lanes cover 128 consecutive n.
    {
        const int lane = tid & 31;
        const int qrow = tid >> 5;            // 0..7
        #pragma unroll
        for (int qi = 0; qi < 4; ++qi) {
            const int q  = qrow + qi * 8;     // 0..31
            const int qg = qBase + q;
            if (qg < CH * NBINS) {
                const float4 v = __ldg((const float4*)
                    (g_scratch + (size_t)qg * NPAD + nBase + lane * 4));
                float* t = tile + q * TS + lane * 4;
                t[0] = v.x; t[1] = v.y; t[2] = v.z; t[3] = v.w;
            }
        }
    }
    __syncthreads();

    // Store: half-warp covers a 128B contiguous q-span of one output row.
    {
        const int c2 = tid & 15;              // q pair: qBase + 2*c2
        const int nr = tid >> 4;              // 0..15
        const int q0 = qBase + 2 * c2;
        if (q0 + 1 < CH * NBINS) {
            #pragma unroll
            for (int k = 0; k < 8; ++k) {
                const int nl = nr + k * 16;   // 0..127
                const int ng = nBase + nl;
                if (ng < N) {
                    float2 v;
                    v.x = tile[(2 * c2)     * TS + nl];
                    v.y = tile[(2 * c2 + 1) * TS + nl];
                    *(float2*)(out + (size_t)ng * (CH * NBINS) + q0) = v;
                }
            }
        }
    }
}

extern "C" void kernel_launch(void* const* d_in, const int* in_sizes, int n_in,
                              void* d_out, int out_size)
{
    const float* ft   = (const float*)d_in[0];   // 490*34*34 floats
    const float* rois = (const float*)d_in[1];   // N*5 floats
    float* out        = (float*)d_out;           // N*10*49 floats

    const int N = in_sizes[1] / 5;
    const int half = (N + 1) / 2;

    dim3 grid0((half + TPB - 1) / TPB, PH + PW);
    weights_kernel<<<grid0, TPB>>>(rois, N, half);

    dim3 grid1((N + RPB - 1) / RPB, NBINS);
    psroi_kernel<<<grid1, TPB>>>(ft, N);

    dim3 grid2((N + TN - 1) / TN, (CH * NBINS + TQ - 1) / TQ);
    transpose_kernel<<<grid2, 256>>>(out, N);
}